// round 13
// baseline (speedup 1.0000x reference)
#include <cuda_runtime.h>
#include <cuda_fp16.h>
#include <cstdint>

#define D_MODEL 2048
#define HIDDEN 1024
#define NUM_EXPERTS 8
#define TPE 2048
#define TOTAL_TOKENS 16384

// fp16 copies (single-pass HMMA everywhere; 5 calibrated rounding sources
// ~2.57e-4 RMS each -> ~5.1e-4 measured, under the 1e-3 gate).
__device__ __half g_xh [(size_t)TOTAL_TOKENS * D_MODEL];
__device__ __half g_wugh[(size_t)2 * NUM_EXPERTS * HIDDEN * D_MODEL];
__device__ __half g_wdh [(size_t)D_MODEL * NUM_EXPERTS * HIDDEN];
__device__ __half g_hh  [(size_t)TOTAL_TOKENS * HIDDEN];

// ---------------- helpers ----------------
// 64B rows; XOR bits[5:4] with bits[8:7] -> conflict-free ldmatrix & cp.async STS
__device__ __forceinline__ uint32_t SW64(uint32_t off) {
    return off ^ ((off >> 3) & 0x30);
}

__device__ __forceinline__ uint32_t smem_u32(const void* p) {
    return (uint32_t)__cvta_generic_to_shared(p);
}

__device__ __forceinline__ void mma_f16(float* c, const uint32_t* a,
                                        uint32_t b0, uint32_t b1) {
    asm volatile(
        "mma.sync.aligned.m16n8k16.row.col.f32.f16.f16.f32 "
        "{%0,%1,%2,%3}, {%4,%5,%6,%7}, {%8,%9}, {%0,%1,%2,%3};"
        : "+f"(c[0]), "+f"(c[1]), "+f"(c[2]), "+f"(c[3])
        : "r"(a[0]), "r"(a[1]), "r"(a[2]), "r"(a[3]), "r"(b0), "r"(b1));
}

__device__ __forceinline__ void ldsm4(uint32_t r[4], uint32_t saddr) {
    asm volatile("ldmatrix.sync.aligned.m8n8.x4.shared.b16 {%0,%1,%2,%3}, [%4];"
                 : "=r"(r[0]), "=r"(r[1]), "=r"(r[2]), "=r"(r[3]) : "r"(saddr));
}

#define CP_ASYNC16(dst, src) \
    asm volatile("cp.async.cg.shared.global [%0], [%1], 16;" :: "r"(dst), "l"(src))
#define CP_COMMIT() asm volatile("cp.async.commit_group;" ::: "memory")
#define CP_WAIT0()  asm volatile("cp.async.wait_group 0;" ::: "memory")

__device__ __forceinline__ float silu(float x) {
    return x / (1.0f + __expf(-x));
}

// Stage (one k32): A[0,8K) fp16 (128 rows x 64B), B[8K,16K) (128 rows x 64B)
#define STAGE 16384
#define SMEM_TOTAL (4 * STAGE)     // 64 KB -> 2 CTAs/SM

// ---------------- split kernel: fp32 -> fp16 ----------------
__global__ void split_h_kernel(const float4* __restrict__ src,
                               uint2* __restrict__ dst, long n4)
{
    for (long i = (long)blockIdx.x * blockDim.x + threadIdx.x; i < n4;
         i += (long)gridDim.x * blockDim.x) {
        float4 v = src[i];
        __half2 p0(__float2half_rn(v.x), __float2half_rn(v.y));
        __half2 p1(__float2half_rn(v.z), __float2half_rn(v.w));
        uint2 o;
        o.x = *reinterpret_cast<uint32_t*>(&p0);
        o.y = *reinterpret_cast<uint32_t*>(&p1);
        dst[i] = o;
    }
}

// ---------------- compute: one k32 stage, warp tile 64x64, single pass -------
// acc[4][8][4]: 4 m-tiles x 8 n-tiles. 8 ldsm.x4 -> 32 HMMA per k16.
__device__ __forceinline__ void compute_k32(uint32_t st, float acc[4][8][4],
                                            int lane, int mw, int nw)
{
    const int r = lane & 15;
    const uint32_t h16 = (uint32_t)(lane >> 4) << 4;

    #pragma unroll
    for (int ks = 0; ks < 2; ks++) {
        const uint32_t kc = (uint32_t)ks * 32 + h16;
        uint32_t a[4][4], b[4][4];

        #pragma unroll
        for (int mt = 0; mt < 4; mt++) {
            uint32_t R = (uint32_t)(mw * 64 + mt * 16 + r) * 64;
            ldsm4(a[mt], st + R + (kc ^ ((R >> 3) & 0x30)));
        }
        #pragma unroll
        for (int pr = 0; pr < 4; pr++) {
            uint32_t R = (uint32_t)(nw * 64 + pr * 16 + r) * 64;
            ldsm4(b[pr], st + 8192 + (R + (kc ^ ((R >> 3) & 0x30))));
        }

        #pragma unroll
        for (int mt = 0; mt < 4; mt++)
            #pragma unroll
            for (int nt = 0; nt < 8; nt++)
                mma_f16(acc[mt][nt], a[mt], b[nt >> 1][nt & 1], b[nt >> 1][(nt & 1) + 2]);
    }
}

// ---------------- kernel 1: h = silu(x@Wg^T) * (x@Wu^T) ----------------
// CTA: 128 tokens x 128 B-rows (64 h-cols; gate/up interleaved per 32 rows).
// 4 warps = 2 mw x 2 nw; warp tile 64 x 64. Two k32 chunks per barrier.
__global__ __launch_bounds__(128, 2)
void moe_upgate_kernel()
{
    extern __shared__ char smem[];
    const uint32_t smem_b = smem_u32(smem);

    const int tid = threadIdx.x;
    const int lane = tid & 31, warp = tid >> 5;
    const int g = lane >> 2, tg = lane & 3;
    const int nw = warp & 1, mw = warp >> 1;

    const int e = blockIdx.z;
    const int m0 = blockIdx.y * 128;
    const int n0 = blockIdx.x * 64;        // h-col base

    const long arow0 = (long)e * TPE + m0;
    const long brow0 = (long)e * 2 * HIDDEN;

    // cp.async: thread tid owns row tid of A and of B (4 x 16B chunks each)
    uint32_t dR[4];
    #pragma unroll
    for (int c = 0; c < 4; c++)
        dR[c] = SW64((uint32_t)(tid * 64 + c * 16));

    const __half* pA = g_xh + (arow0 + tid) * D_MODEL;
    // B row j (0..127): warp nwr=j>>6, pgu=(j>>5)&1 (0=gate,1=up), cc=j&31
    const int nwr = tid >> 6, pgu = (tid >> 5) & 1, cc = tid & 31;
    const long grow = brow0 + (pgu ? HIDDEN : 0) + n0 + nwr * 32 + cc;
    const __half* pB = g_wugh + grow * D_MODEL;

    #define ISSUE_UG(SIDX, K0) do { \
        uint32_t _s = smem_b + (uint32_t)(SIDX) * STAGE; \
        _Pragma("unroll") \
        for (int _c = 0; _c < 4; _c++) { \
            CP_ASYNC16(_s + dR[_c], pA + (K0) + _c * 8); \
            CP_ASYNC16(_s + 8192 + dR[_c], pB + (K0) + _c * 8); \
        } \
    } while (0)

    float acc[4][8][4];
    #pragma unroll
    for (int i = 0; i < 4; i++)
        #pragma unroll
        for (int j = 0; j < 8; j++)
            #pragma unroll
            for (int k = 0; k < 4; k++) acc[i][j][k] = 0.0f;

    const int NPAIR = (D_MODEL / 32) / 2;   // 32 pairs

    ISSUE_UG(0, 0);
    ISSUE_UG(1, 32);
    CP_COMMIT();

    for (int p = 0; p < NPAIR; p++) {
        CP_WAIT0();
        __syncthreads();
        if (p + 1 < NPAIR) {
            ISSUE_UG((2 * p + 2) & 3, (long)(2 * p + 2) * 32);
            ISSUE_UG((2 * p + 3) & 3, (long)(2 * p + 3) * 32);
            CP_COMMIT();
        }
        compute_k32(smem_b + (uint32_t)((2 * p) & 3) * STAGE, acc, lane, mw, nw);
        compute_k32(smem_b + (uint32_t)((2 * p + 1) & 3) * STAGE, acc, lane, mw, nw);
    }
    #undef ISSUE_UG

    // epilogue: nt 0..3 = gate (B rows nw*64+0..31), nt 4..7 = matching up
    #pragma unroll
    for (int mt = 0; mt < 4; mt++) {
        long row0 = arow0 + mw * 64 + mt * 16 + g;
        #pragma unroll
        for (int nt = 0; nt < 4; nt++) {
            const float* ga = acc[mt][nt];
            const float* ua = acc[mt][nt + 4];
            int col = n0 + nw * 32 + nt * 8 + tg * 2;
            __half2 v0(__float2half_rn(silu(ga[0]) * ua[0]),
                       __float2half_rn(silu(ga[1]) * ua[1]));
            __half2 v1(__float2half_rn(silu(ga[2]) * ua[2]),
                       __float2half_rn(silu(ga[3]) * ua[3]));
            *reinterpret_cast<__half2*>(g_hh + row0 * HIDDEN + col) = v0;
            *reinterpret_cast<__half2*>(g_hh + (row0 + 8) * HIDDEN + col) = v1;
        }
    }
}

// ---------------- kernel 2: out = h @ Wd^T ----------------
// CTA: 128 tokens x 128 out-cols; 4 warps, warp tile 64 x 64.
__global__ __launch_bounds__(128, 2)
void moe_down_kernel(float* __restrict__ out)
{
    extern __shared__ char smem[];
    const uint32_t smem_b = smem_u32(smem);

    const int tid = threadIdx.x;
    const int lane = tid & 31, warp = tid >> 5;
    const int g = lane >> 2, tg = lane & 3;
    const int nw = warp & 1, mw = warp >> 1;

    const int e = blockIdx.z;
    const int m0 = blockIdx.y * 128;
    const int n0 = blockIdx.x * 128;

    const long arow0 = (long)e * TPE + m0;

    uint32_t dR[4];
    #pragma unroll
    for (int c = 0; c < 4; c++)
        dR[c] = SW64((uint32_t)(tid * 64 + c * 16));

    const __half* pA = g_hh + (arow0 + tid) * HIDDEN;
    const long browb = (long)(n0 + tid) * (NUM_EXPERTS * HIDDEN) + (long)e * HIDDEN;
    const __half* pB = g_wdh + browb;

    #define ISSUE_DN(SIDX, K0) do { \
        uint32_t _s = smem_b + (uint32_t)(SIDX) * STAGE; \
        _Pragma("unroll") \
        for (int _c = 0; _c < 4; _c++) { \
            CP_ASYNC16(_s + dR[_c], pA + (K0) + _c * 8); \
            CP_ASYNC16(_s + 8192 + dR[_c], pB + (K0) + _c * 8); \
        } \
    } while (0)

    float acc[4][8][4];
    #pragma unroll
    for (int i = 0; i < 4; i++)
        #pragma unroll
        for (int j = 0; j < 8; j++)
            #pragma unroll
            for (int k = 0; k < 4; k++) acc[i][j][k] = 0.0f;

    const int NPAIR = (HIDDEN / 32) / 2;    // 16 pairs

    ISSUE_DN(0, 0);
    ISSUE_DN(1, 32);
    CP_COMMIT();

    for (int p = 0; p < NPAIR; p++) {
        CP_WAIT0();
        __syncthreads();
        if (p + 1 < NPAIR) {
            ISSUE_DN((2 * p + 2) & 3, (long)(2 * p + 2) * 32);
            ISSUE_DN((2 * p + 3) & 3, (long)(2 * p + 3) * 32);
            CP_COMMIT();
        }
        compute_k32(smem_b + (uint32_t)((2 * p) & 3) * STAGE, acc, lane, mw, nw);
        compute_k32(smem_b + (uint32_t)((2 * p + 1) & 3) * STAGE, acc, lane, mw, nw);
    }
    #undef ISSUE_DN

    #pragma unroll
    for (int mt = 0; mt < 4; mt++) {
        long row0 = arow0 + mw * 64 + mt * 16 + g;
        #pragma unroll
        for (int nt = 0; nt < 8; nt++) {
            int col = n0 + nw * 64 + nt * 8 + tg * 2;
            float2 v0, v1;
            v0.x = acc[mt][nt][0]; v0.y = acc[mt][nt][1];
            v1.x = acc[mt][nt][2]; v1.y = acc[mt][nt][3];
            *reinterpret_cast<float2*>(out + row0 * D_MODEL + col) = v0;
            *reinterpret_cast<float2*>(out + (row0 + 8) * D_MODEL + col) = v1;
        }
    }
}

// ---------------- launch ----------------
extern "C" void kernel_launch(void* const* d_in, const int* in_sizes, int n_in,
                              void* d_out, int out_size)
{
    const float* x        = (const float*)d_in[0];  // [16384, 2048]
    const float* w_upgate = (const float*)d_in[1];  // [E*2H, D]
    const float* w_down   = (const float*)d_in[2];  // [D, E*H]
    float* out = (float*)d_out;

    cudaFuncSetAttribute(moe_upgate_kernel,
                         cudaFuncAttributeMaxDynamicSharedMemorySize, SMEM_TOTAL);
    cudaFuncSetAttribute(moe_down_kernel,
                         cudaFuncAttributeMaxDynamicSharedMemorySize, SMEM_TOTAL);

    __half *xh, *ugh, *wdh;
    cudaGetSymbolAddress((void**)&xh,  g_xh);
    cudaGetSymbolAddress((void**)&ugh, g_wugh);
    cudaGetSymbolAddress((void**)&wdh, g_wdh);

    {
        long n4x  = (long)TOTAL_TOKENS * D_MODEL / 4;
        long n4ug = (long)2 * NUM_EXPERTS * HIDDEN * D_MODEL / 4;
        long n4wd = (long)D_MODEL * NUM_EXPERTS * HIDDEN / 4;
        split_h_kernel<<<2048, 256>>>((const float4*)x, (uint2*)xh, n4x);
        split_h_kernel<<<2048, 256>>>((const float4*)w_upgate, (uint2*)ugh, n4ug);
        split_h_kernel<<<2048, 256>>>((const float4*)w_down, (uint2*)wdh, n4wd);
    }

    {
        dim3 grid(HIDDEN / 64, TPE / 128, NUM_EXPERTS);    // (16,16,8)
        moe_upgate_kernel<<<grid, 128, SMEM_TOTAL>>>();
    }
    {
        dim3 grid(D_MODEL / 128, TPE / 128, NUM_EXPERTS);  // (16,16,8)
        moe_down_kernel<<<grid, 128, SMEM_TOTAL>>>(out);
    }
}

// round 14
// speedup vs baseline: 1.0002x; 1.0002x over previous
#include <cuda_runtime.h>
#include <cuda_fp16.h>
#include <cstdint>

#define D_MODEL 2048
#define HIDDEN 1024
#define NUM_EXPERTS 8
#define TPE 2048
#define TOTAL_TOKENS 16384

// fp16 copies (single-pass HMMA everywhere; 5 calibrated rounding sources
// ~2.57e-4 RMS each -> ~5.1e-4 measured, under the 1e-3 gate).
__device__ __half g_xh [(size_t)TOTAL_TOKENS * D_MODEL];
__device__ __half g_wugh[(size_t)2 * NUM_EXPERTS * HIDDEN * D_MODEL];
__device__ __half g_wdh [(size_t)D_MODEL * NUM_EXPERTS * HIDDEN];
__device__ __half g_hh  [(size_t)TOTAL_TOKENS * HIDDEN];

// ---------------- helpers ----------------
// 64B rows; XOR bits[5:4] with bits[8:7] -> conflict-free ldmatrix & cp.async STS
__device__ __forceinline__ uint32_t SW64(uint32_t off) {
    return off ^ ((off >> 3) & 0x30);
}

__device__ __forceinline__ uint32_t smem_u32(const void* p) {
    return (uint32_t)__cvta_generic_to_shared(p);
}

__device__ __forceinline__ void mma_f16(float* c, const uint32_t* a,
                                        uint32_t b0, uint32_t b1) {
    asm volatile(
        "mma.sync.aligned.m16n8k16.row.col.f32.f16.f16.f32 "
        "{%0,%1,%2,%3}, {%4,%5,%6,%7}, {%8,%9}, {%0,%1,%2,%3};"
        : "+f"(c[0]), "+f"(c[1]), "+f"(c[2]), "+f"(c[3])
        : "r"(a[0]), "r"(a[1]), "r"(a[2]), "r"(a[3]), "r"(b0), "r"(b1));
}

__device__ __forceinline__ void ldsm4(uint32_t r[4], uint32_t saddr) {
    asm volatile("ldmatrix.sync.aligned.m8n8.x4.shared.b16 {%0,%1,%2,%3}, [%4];"
                 : "=r"(r[0]), "=r"(r[1]), "=r"(r[2]), "=r"(r[3]) : "r"(saddr));
}

#define CP_ASYNC16(dst, src) \
    asm volatile("cp.async.cg.shared.global [%0], [%1], 16;" :: "r"(dst), "l"(src))
#define CP_COMMIT() asm volatile("cp.async.commit_group;" ::: "memory")
#define CP_WAIT0()  asm volatile("cp.async.wait_group 0;" ::: "memory")

__device__ __forceinline__ float silu(float x) {
    return x / (1.0f + __expf(-x));
}

// Stage (one k32): A[0,8K) fp16 (128 rows x 64B), B[8K,16K) (128 rows x 64B)
#define STAGE 16384
#define SMEM_TOTAL (4 * STAGE)     // 64 KB -> 2 CTAs/SM

// ---------------- split kernel: fp32 -> fp16 ----------------
__global__ void split_h_kernel(const float4* __restrict__ src,
                               uint2* __restrict__ dst, long n4)
{
    for (long i = (long)blockIdx.x * blockDim.x + threadIdx.x; i < n4;
         i += (long)gridDim.x * blockDim.x) {
        float4 v = src[i];
        __half2 p0(__float2half_rn(v.x), __float2half_rn(v.y));
        __half2 p1(__float2half_rn(v.z), __float2half_rn(v.w));
        uint2 o;
        o.x = *reinterpret_cast<uint32_t*>(&p0);
        o.y = *reinterpret_cast<uint32_t*>(&p1);
        dst[i] = o;
    }
}

// ---------------- fragment pipeline pieces (warp tile 64x64) ----------------
struct Frag {
    uint32_t a[4][4];
    uint32_t b[4][4];
};

// load frags for one k16 half (ks=0/1) of a k32 stage
__device__ __forceinline__ void load_frags(uint32_t st, int ks, Frag& f,
                                           int lane, int mw, int nw)
{
    const int r = lane & 15;
    const uint32_t kc = (uint32_t)ks * 32 + (((uint32_t)(lane >> 4)) << 4);

    #pragma unroll
    for (int mt = 0; mt < 4; mt++) {
        uint32_t R = (uint32_t)(mw * 64 + mt * 16 + r) * 64;
        ldsm4(f.a[mt], st + R + (kc ^ ((R >> 3) & 0x30)));
    }
    #pragma unroll
    for (int pr = 0; pr < 4; pr++) {
        uint32_t R = (uint32_t)(nw * 64 + pr * 16 + r) * 64;
        ldsm4(f.b[pr], st + 8192 + (R + (kc ^ ((R >> 3) & 0x30))));
    }
}

// 32 HMMA from one frag set
__device__ __forceinline__ void mma_frags(const Frag& f, float acc[4][8][4])
{
    #pragma unroll
    for (int mt = 0; mt < 4; mt++)
        #pragma unroll
        for (int nt = 0; nt < 8; nt++)
            mma_f16(acc[mt][nt], f.a[mt],
                    f.b[nt >> 1][nt & 1], f.b[nt >> 1][(nt & 1) + 2]);
}

// ---------------- kernel 1: h = silu(x@Wg^T) * (x@Wu^T) ----------------
// CTA: 128 tokens x 128 B-rows (64 h-cols; gate/up interleaved per 32 rows).
// 4 warps = 2 mw x 2 nw; warp tile 64 x 64. Two k32 stages per barrier,
// register-fragment double buffering across the 4 k16 steps.
__global__ __launch_bounds__(128, 2)
void moe_upgate_kernel()
{
    extern __shared__ char smem[];
    const uint32_t smem_b = smem_u32(smem);

    const int tid = threadIdx.x;
    const int lane = tid & 31, warp = tid >> 5;
    const int g = lane >> 2, tg = lane & 3;
    const int nw = warp & 1, mw = warp >> 1;

    const int e = blockIdx.z;
    const int m0 = blockIdx.y * 128;
    const int n0 = blockIdx.x * 64;        // h-col base

    const long arow0 = (long)e * TPE + m0;
    const long brow0 = (long)e * 2 * HIDDEN;

    // cp.async: thread tid owns row tid of A and of B (4 x 16B chunks each)
    uint32_t dR[4];
    #pragma unroll
    for (int c = 0; c < 4; c++)
        dR[c] = SW64((uint32_t)(tid * 64 + c * 16));

    const __half* pA = g_xh + (arow0 + tid) * D_MODEL;
    // B row j (0..127): warp nwr=j>>6, pgu=(j>>5)&1 (0=gate,1=up), cc=j&31
    const int nwr = tid >> 6, pgu = (tid >> 5) & 1, cc = tid & 31;
    const long grow = brow0 + (pgu ? HIDDEN : 0) + n0 + nwr * 32 + cc;
    const __half* pB = g_wugh + grow * D_MODEL;

    #define ISSUE_UG(SIDX, K0) do { \
        uint32_t _s = smem_b + (uint32_t)(SIDX) * STAGE; \
        _Pragma("unroll") \
        for (int _c = 0; _c < 4; _c++) { \
            CP_ASYNC16(_s + dR[_c], pA + (K0) + _c * 8); \
            CP_ASYNC16(_s + 8192 + dR[_c], pB + (K0) + _c * 8); \
        } \
    } while (0)

    float acc[4][8][4];
    #pragma unroll
    for (int i = 0; i < 4; i++)
        #pragma unroll
        for (int j = 0; j < 8; j++)
            #pragma unroll
            for (int k = 0; k < 4; k++) acc[i][j][k] = 0.0f;

    const int NPAIR = (D_MODEL / 32) / 2;   // 32 pairs

    ISSUE_UG(0, 0);
    ISSUE_UG(1, 32);
    CP_COMMIT();

    Frag f0, f1;
    for (int p = 0; p < NPAIR; p++) {
        const uint32_t s0 = smem_b + (uint32_t)((2 * p) & 3) * STAGE;
        const uint32_t s1 = smem_b + (uint32_t)((2 * p + 1) & 3) * STAGE;

        CP_WAIT0();
        __syncthreads();
        if (p + 1 < NPAIR) {
            ISSUE_UG((2 * p + 2) & 3, (long)(2 * p + 2) * 32);
            ISSUE_UG((2 * p + 3) & 3, (long)(2 * p + 3) * 32);
            CP_COMMIT();
        }
        // 4 k16 steps, frags double-buffered: LDSM of step i+1 overlaps MMA of i
        load_frags(s0, 0, f0, lane, mw, nw);
        load_frags(s0, 1, f1, lane, mw, nw);
        mma_frags(f0, acc);
        load_frags(s1, 0, f0, lane, mw, nw);
        mma_frags(f1, acc);
        load_frags(s1, 1, f1, lane, mw, nw);
        mma_frags(f0, acc);
        mma_frags(f1, acc);
    }
    #undef ISSUE_UG

    // epilogue: nt 0..3 = gate (B rows nw*64+0..31), nt 4..7 = matching up
    #pragma unroll
    for (int mt = 0; mt < 4; mt++) {
        long row0 = arow0 + mw * 64 + mt * 16 + g;
        #pragma unroll
        for (int nt = 0; nt < 4; nt++) {
            const float* ga = acc[mt][nt];
            const float* ua = acc[mt][nt + 4];
            int col = n0 + nw * 32 + nt * 8 + tg * 2;
            __half2 v0(__float2half_rn(silu(ga[0]) * ua[0]),
                       __float2half_rn(silu(ga[1]) * ua[1]));
            __half2 v1(__float2half_rn(silu(ga[2]) * ua[2]),
                       __float2half_rn(silu(ga[3]) * ua[3]));
            *reinterpret_cast<__half2*>(g_hh + row0 * HIDDEN + col) = v0;
            *reinterpret_cast<__half2*>(g_hh + (row0 + 8) * HIDDEN + col) = v1;
        }
    }
}

// ---------------- kernel 2: out = h @ Wd^T ----------------
// CTA: 128 tokens x 128 out-cols; 4 warps, warp tile 64 x 64, frag pipelined.
__global__ __launch_bounds__(128, 2)
void moe_down_kernel(float* __restrict__ out)
{
    extern __shared__ char smem[];
    const uint32_t smem_b = smem_u32(smem);

    const int tid = threadIdx.x;
    const int lane = tid & 31, warp = tid >> 5;
    const int g = lane >> 2, tg = lane & 3;
    const int nw = warp & 1, mw = warp >> 1;

    const int e = blockIdx.z;
    const int m0 = blockIdx.y * 128;
    const int n0 = blockIdx.x * 128;

    const long arow0 = (long)e * TPE + m0;

    uint32_t dR[4];
    #pragma unroll
    for (int c = 0; c < 4; c++)
        dR[c] = SW64((uint32_t)(tid * 64 + c * 16));

    const __half* pA = g_hh + (arow0 + tid) * HIDDEN;
    const long browb = (long)(n0 + tid) * (NUM_EXPERTS * HIDDEN) + (long)e * HIDDEN;
    const __half* pB = g_wdh + browb;

    #define ISSUE_DN(SIDX, K0) do { \
        uint32_t _s = smem_b + (uint32_t)(SIDX) * STAGE; \
        _Pragma("unroll") \
        for (int _c = 0; _c < 4; _c++) { \
            CP_ASYNC16(_s + dR[_c], pA + (K0) + _c * 8); \
            CP_ASYNC16(_s + 8192 + dR[_c], pB + (K0) + _c * 8); \
        } \
    } while (0)

    float acc[4][8][4];
    #pragma unroll
    for (int i = 0; i < 4; i++)
        #pragma unroll
        for (int j = 0; j < 8; j++)
            #pragma unroll
            for (int k = 0; k < 4; k++) acc[i][j][k] = 0.0f;

    const int NPAIR = (HIDDEN / 32) / 2;    // 16 pairs

    ISSUE_DN(0, 0);
    ISSUE_DN(1, 32);
    CP_COMMIT();

    Frag f0, f1;
    for (int p = 0; p < NPAIR; p++) {
        const uint32_t s0 = smem_b + (uint32_t)((2 * p) & 3) * STAGE;
        const uint32_t s1 = smem_b + (uint32_t)((2 * p + 1) & 3) * STAGE;

        CP_WAIT0();
        __syncthreads();
        if (p + 1 < NPAIR) {
            ISSUE_DN((2 * p + 2) & 3, (long)(2 * p + 2) * 32);
            ISSUE_DN((2 * p + 3) & 3, (long)(2 * p + 3) * 32);
            CP_COMMIT();
        }
        load_frags(s0, 0, f0, lane, mw, nw);
        load_frags(s0, 1, f1, lane, mw, nw);
        mma_frags(f0, acc);
        load_frags(s1, 0, f0, lane, mw, nw);
        mma_frags(f1, acc);
        load_frags(s1, 1, f1, lane, mw, nw);
        mma_frags(f0, acc);
        mma_frags(f1, acc);
    }
    #undef ISSUE_DN

    #pragma unroll
    for (int mt = 0; mt < 4; mt++) {
        long row0 = arow0 + mw * 64 + mt * 16 + g;
        #pragma unroll
        for (int nt = 0; nt < 8; nt++) {
            int col = n0 + nw * 64 + nt * 8 + tg * 2;
            float2 v0, v1;
            v0.x = acc[mt][nt][0]; v0.y = acc[mt][nt][1];
            v1.x = acc[mt][nt][2]; v1.y = acc[mt][nt][3];
            *reinterpret_cast<float2*>(out + row0 * D_MODEL + col) = v0;
            *reinterpret_cast<float2*>(out + (row0 + 8) * D_MODEL + col) = v1;
        }
    }
}

// ---------------- launch ----------------
extern "C" void kernel_launch(void* const* d_in, const int* in_sizes, int n_in,
                              void* d_out, int out_size)
{
    const float* x        = (const float*)d_in[0];  // [16384, 2048]
    const float* w_upgate = (const float*)d_in[1];  // [E*2H, D]
    const float* w_down   = (const float*)d_in[2];  // [D, E*H]
    float* out = (float*)d_out;

    cudaFuncSetAttribute(moe_upgate_kernel,
                         cudaFuncAttributeMaxDynamicSharedMemorySize, SMEM_TOTAL);
    cudaFuncSetAttribute(moe_down_kernel,
                         cudaFuncAttributeMaxDynamicSharedMemorySize, SMEM_TOTAL);

    __half *xh, *ugh, *wdh;
    cudaGetSymbolAddress((void**)&xh,  g_xh);
    cudaGetSymbolAddress((void**)&ugh, g_wugh);
    cudaGetSymbolAddress((void**)&wdh, g_wdh);

    {
        long n4x  = (long)TOTAL_TOKENS * D_MODEL / 4;
        long n4ug = (long)2 * NUM_EXPERTS * HIDDEN * D_MODEL / 4;
        long n4wd = (long)D_MODEL * NUM_EXPERTS * HIDDEN / 4;
        split_h_kernel<<<2048, 256>>>((const float4*)x, (uint2*)xh, n4x);
        split_h_kernel<<<2048, 256>>>((const float4*)w_upgate, (uint2*)ugh, n4ug);
        split_h_kernel<<<2048, 256>>>((const float4*)w_down, (uint2*)wdh, n4wd);
    }

    {
        dim3 grid(HIDDEN / 64, TPE / 128, NUM_EXPERTS);    // (16,16,8)
        moe_upgate_kernel<<<grid, 128, SMEM_TOTAL>>>();
    }
    {
        dim3 grid(D_MODEL / 128, TPE / 128, NUM_EXPERTS);  // (16,16,8)
        moe_down_kernel<<<grid, 128, SMEM_TOTAL>>>(out);
    }
}

// round 15
// speedup vs baseline: 1.6627x; 1.6624x over previous
#include <cuda_runtime.h>
#include <cuda_fp16.h>
#include <cstdint>

#define D_MODEL 2048
#define HIDDEN 1024
#define NUM_EXPERTS 8
#define TPE 2048
#define TOTAL_TOKENS 16384

// fp16 copies (single-pass HMMA everywhere; 5 calibrated rounding sources
// ~2.57e-4 RMS each -> 5.14e-4 measured, under the 1e-3 gate).
__device__ __half g_xh [(size_t)TOTAL_TOKENS * D_MODEL];
__device__ __half g_wugh[(size_t)2 * NUM_EXPERTS * HIDDEN * D_MODEL];
__device__ __half g_wdh [(size_t)D_MODEL * NUM_EXPERTS * HIDDEN];
__device__ __half g_hh  [(size_t)TOTAL_TOKENS * HIDDEN];

// ---------------- helpers ----------------
// 64B rows; XOR bits[5:4] with bits[8:7] -> conflict-free ldmatrix & cp.async STS
__device__ __forceinline__ uint32_t SW64(uint32_t off) {
    return off ^ ((off >> 3) & 0x30);
}

__device__ __forceinline__ uint32_t smem_u32(const void* p) {
    return (uint32_t)__cvta_generic_to_shared(p);
}

__device__ __forceinline__ void mma_f16(float* c, const uint32_t* a,
                                        uint32_t b0, uint32_t b1) {
    asm volatile(
        "mma.sync.aligned.m16n8k16.row.col.f32.f16.f16.f32 "
        "{%0,%1,%2,%3}, {%4,%5,%6,%7}, {%8,%9}, {%0,%1,%2,%3};"
        : "+f"(c[0]), "+f"(c[1]), "+f"(c[2]), "+f"(c[3])
        : "r"(a[0]), "r"(a[1]), "r"(a[2]), "r"(a[3]), "r"(b0), "r"(b1));
}

__device__ __forceinline__ void ldsm4(uint32_t r[4], uint32_t saddr) {
    asm volatile("ldmatrix.sync.aligned.m8n8.x4.shared.b16 {%0,%1,%2,%3}, [%4];"
                 : "=r"(r[0]), "=r"(r[1]), "=r"(r[2]), "=r"(r[3]) : "r"(saddr));
}

#define CP_ASYNC16(dst, src) \
    asm volatile("cp.async.cg.shared.global [%0], [%1], 16;" :: "r"(dst), "l"(src))
#define CP_COMMIT() asm volatile("cp.async.commit_group;" ::: "memory")
#define CP_WAIT0()  asm volatile("cp.async.wait_group 0;" ::: "memory")

__device__ __forceinline__ float silu(float x) {
    return x / (1.0f + __expf(-x));
}

// Stage (one k32): A[0,16K) fp16 (256 rows x 64B), B[16K,20K) (64 rows x 64B)
#define STAGE 20480
#define SMEM_TOTAL (4 * STAGE)     // 80 KB -> 2 CTAs/SM

// Precomputed swizzled ldsm offsets: [ks][frag]; A frags 0..3, B frags 0..1
struct LdsmOffs {
    uint32_t a[2][4];
    uint32_t b[2][2];
};

__device__ __forceinline__ LdsmOffs make_offs(int lane, int mw, int nw) {
    LdsmOffs o;
    const int r = lane & 15;
    const uint32_t h16 = (uint32_t)(lane >> 4) << 4;
    #pragma unroll
    for (int ks = 0; ks < 2; ks++) {
        const uint32_t kc = (uint32_t)ks * 32 + h16;
        #pragma unroll
        for (int mt = 0; mt < 4; mt++) {
            uint32_t R = (uint32_t)(mw * 64 + mt * 16 + r) * 64;
            o.a[ks][mt] = R + (kc ^ ((R >> 3) & 0x30));
        }
        #pragma unroll
        for (int pr = 0; pr < 2; pr++) {
            uint32_t R = (uint32_t)(nw * 32 + pr * 16 + r) * 64;
            o.b[ks][pr] = 16384u + R + (kc ^ ((R >> 3) & 0x30));
        }
    }
    return o;
}

// ---------------- split kernel: fp32 -> fp16 ----------------
__global__ void split_h_kernel(const float4* __restrict__ src,
                               uint2* __restrict__ dst, long n4)
{
    for (long i = (long)blockIdx.x * blockDim.x + threadIdx.x; i < n4;
         i += (long)gridDim.x * blockDim.x) {
        float4 v = src[i];
        __half2 p0(__float2half_rn(v.x), __float2half_rn(v.y));
        __half2 p1(__float2half_rn(v.z), __float2half_rn(v.w));
        uint2 o;
        o.x = *reinterpret_cast<uint32_t*>(&p0);
        o.y = *reinterpret_cast<uint32_t*>(&p1);
        dst[i] = o;
    }
}

// ---------------- compute: one k32 stage, warp tile 64x32, single pass -------
__device__ __forceinline__ void compute_k32(uint32_t st, float acc[4][4][4],
                                            const LdsmOffs& o)
{
    #pragma unroll
    for (int ks = 0; ks < 2; ks++) {
        uint32_t a[4][4], bh[2][4];

        #pragma unroll
        for (int mt = 0; mt < 4; mt++)
            ldsm4(a[mt], st + o.a[ks][mt]);
        #pragma unroll
        for (int pr = 0; pr < 2; pr++)
            ldsm4(bh[pr], st + o.b[ks][pr]);

        #pragma unroll
        for (int mt = 0; mt < 4; mt++)
            #pragma unroll
            for (int nt = 0; nt < 4; nt++)
                mma_f16(acc[mt][nt], a[mt], bh[nt >> 1][nt & 1], bh[nt >> 1][(nt & 1) + 2]);
    }
}

// ---------------- kernel 1: h = silu(x@Wg^T) * (x@Wu^T) ----------------
// CTA: 256 tokens x 64 B-rows (32 h-cols; gate/up interleaved per 16 rows).
// 8 warps = 4 mw x 2 nw; warp tile 64 x 32. Two k32 chunks per barrier,
// two pairs per loop iteration (all stage indices compile-time).
__global__ __launch_bounds__(256, 2)
void moe_upgate_kernel()
{
    extern __shared__ char smem[];
    const uint32_t smem_b = smem_u32(smem);

    const int tid = threadIdx.x;
    const int lane = tid & 31, warp = tid >> 5;
    const int g = lane >> 2, tg = lane & 3;
    const int nw = warp & 1, mw = warp >> 1;

    const int e = blockIdx.z;
    const int m0 = blockIdx.y * 256;
    const int n0 = blockIdx.x * 32;        // h-col base

    const long arow0 = (long)e * TPE + m0;
    const long brow0 = (long)e * 2 * HIDDEN;

    const int trow = tid >> 2, tc16 = tid & 3;
    uint32_t dA[4];
    #pragma unroll
    for (int it = 0; it < 4; it++)
        dA[it] = SW64((uint32_t)((trow + it * 64) * 64 + tc16 * 16));
    const uint32_t dB = SW64((uint32_t)(trow * 64 + tc16 * 16));

    const __half* pA = g_xh + (arow0 + trow) * D_MODEL + tc16 * 8;
    const int nwr = trow >> 5, jj = trow & 31, pgu = jj >> 4, cc = jj & 15;
    const long grow = brow0 + (pgu ? HIDDEN : 0) + n0 + nwr * 16 + cc;
    const __half* pB = g_wugh + grow * D_MODEL + tc16 * 8;

    const LdsmOffs offs = make_offs(lane, mw, nw);

    #define ISSUE_UG(SIDX, PA, PB) do { \
        uint32_t _s = smem_b + (uint32_t)(SIDX) * STAGE; \
        _Pragma("unroll") \
        for (int _it = 0; _it < 4; _it++) \
            CP_ASYNC16(_s + dA[_it], (PA) + (long)_it * 64 * D_MODEL); \
        CP_ASYNC16(_s + 16384 + dB, (PB)); \
    } while (0)

    float acc[4][4][4];
    #pragma unroll
    for (int i = 0; i < 4; i++)
        #pragma unroll
        for (int j = 0; j < 4; j++)
            #pragma unroll
            for (int k = 0; k < 4; k++) acc[i][j][k] = 0.0f;

    // prologue: chunks 0,1 -> stages 0,1
    ISSUE_UG(0, pA, pB);
    ISSUE_UG(1, pA + 32, pB + 32);
    CP_COMMIT();

    const int NQUAD = (D_MODEL / 32) / 4;   // 16 iterations x 4 chunks
    for (int q = 0; q < NQUAD; q++) {
        // pair A: stages 0,1; issue chunks -> stages 2,3
        CP_WAIT0();
        __syncthreads();
        ISSUE_UG(2, pA + 64, pB + 64);
        ISSUE_UG(3, pA + 96, pB + 96);
        CP_COMMIT();
        compute_k32(smem_b + 0 * STAGE, acc, offs);
        compute_k32(smem_b + 1 * STAGE, acc, offs);

        // pair B: stages 2,3; issue chunks -> stages 0,1
        CP_WAIT0();
        __syncthreads();
        if (q + 1 < NQUAD) {
            ISSUE_UG(0, pA + 128, pB + 128);
            ISSUE_UG(1, pA + 160, pB + 160);
        }
        CP_COMMIT();
        compute_k32(smem_b + 2 * STAGE, acc, offs);
        compute_k32(smem_b + 3 * STAGE, acc, offs);

        pA += 128;
        pB += 128;
    }
    #undef ISSUE_UG

    // epilogue: acc[mt][ntl] = gate (pr=0), acc[mt][2+ntl] = up (pr=1)
    #pragma unroll
    for (int mt = 0; mt < 4; mt++) {
        long row0 = arow0 + mw * 64 + mt * 16 + g;
        #pragma unroll
        for (int ntl = 0; ntl < 2; ntl++) {
            const float* ga = acc[mt][ntl];
            const float* ua = acc[mt][2 + ntl];
            int col = n0 + nw * 16 + ntl * 8 + tg * 2;
            __half2 v0(__float2half_rn(silu(ga[0]) * ua[0]),
                       __float2half_rn(silu(ga[1]) * ua[1]));
            __half2 v1(__float2half_rn(silu(ga[2]) * ua[2]),
                       __float2half_rn(silu(ga[3]) * ua[3]));
            *reinterpret_cast<__half2*>(g_hh + row0 * HIDDEN + col) = v0;
            *reinterpret_cast<__half2*>(g_hh + (row0 + 8) * HIDDEN + col) = v1;
        }
    }
}

// ---------------- kernel 2: out = h @ Wd^T ----------------
// CTA: 256 tokens x 64 out-cols; warp tile 64 x 32.
__global__ __launch_bounds__(256, 2)
void moe_down_kernel(float* __restrict__ out)
{
    extern __shared__ char smem[];
    const uint32_t smem_b = smem_u32(smem);

    const int tid = threadIdx.x;
    const int lane = tid & 31, warp = tid >> 5;
    const int g = lane >> 2, tg = lane & 3;
    const int nw = warp & 1, mw = warp >> 1;

    const int e = blockIdx.z;
    const int m0 = blockIdx.y * 256;
    const int n0 = blockIdx.x * 64;

    const long arow0 = (long)e * TPE + m0;

    const int trow = tid >> 2, tc16 = tid & 3;
    uint32_t dA[4];
    #pragma unroll
    for (int it = 0; it < 4; it++)
        dA[it] = SW64((uint32_t)((trow + it * 64) * 64 + tc16 * 16));
    const uint32_t dB = SW64((uint32_t)(trow * 64 + tc16 * 16));

    const __half* pA = g_hh + (arow0 + trow) * HIDDEN + tc16 * 8;
    const long browb = (long)(n0 + trow) * (NUM_EXPERTS * HIDDEN) + (long)e * HIDDEN;
    const __half* pB = g_wdh + browb + tc16 * 8;

    const LdsmOffs offs = make_offs(lane, mw, nw);

    #define ISSUE_DN(SIDX, PA, PB) do { \
        uint32_t _s = smem_b + (uint32_t)(SIDX) * STAGE; \
        _Pragma("unroll") \
        for (int _it = 0; _it < 4; _it++) \
            CP_ASYNC16(_s + dA[_it], (PA) + (long)_it * 64 * HIDDEN); \
        CP_ASYNC16(_s + 16384 + dB, (PB)); \
    } while (0)

    float acc[4][4][4];
    #pragma unroll
    for (int i = 0; i < 4; i++)
        #pragma unroll
        for (int j = 0; j < 4; j++)
            #pragma unroll
            for (int k = 0; k < 4; k++) acc[i][j][k] = 0.0f;

    ISSUE_DN(0, pA, pB);
    ISSUE_DN(1, pA + 32, pB + 32);
    CP_COMMIT();

    const int NQUAD = (HIDDEN / 32) / 4;    // 8 iterations x 4 chunks
    for (int q = 0; q < NQUAD; q++) {
        CP_WAIT0();
        __syncthreads();
        ISSUE_DN(2, pA + 64, pB + 64);
        ISSUE_DN(3, pA + 96, pB + 96);
        CP_COMMIT();
        compute_k32(smem_b + 0 * STAGE, acc, offs);
        compute_k32(smem_b + 1 * STAGE, acc, offs);

        CP_WAIT0();
        __syncthreads();
        if (q + 1 < NQUAD) {
            ISSUE_DN(0, pA + 128, pB + 128);
            ISSUE_DN(1, pA + 160, pB + 160);
        }
        CP_COMMIT();
        compute_k32(smem_b + 2 * STAGE, acc, offs);
        compute_k32(smem_b + 3 * STAGE, acc, offs);

        pA += 128;
        pB += 128;
    }
    #undef ISSUE_DN

    #pragma unroll
    for (int mt = 0; mt < 4; mt++) {
        long row0 = arow0 + mw * 64 + mt * 16 + g;
        #pragma unroll
        for (int nt = 0; nt < 4; nt++) {
            int col = n0 + nw * 32 + (nt >> 1) * 16 + (nt & 1) * 8 + tg * 2;
            float2 v0, v1;
            v0.x = acc[mt][nt][0]; v0.y = acc[mt][nt][1];
            v1.x = acc[mt][nt][2]; v1.y = acc[mt][nt][3];
            *reinterpret_cast<float2*>(out + row0 * D_MODEL + col) = v0;
            *reinterpret_cast<float2*>(out + (row0 + 8) * D_MODEL + col) = v1;
        }
    }
}

// ---------------- launch ----------------
extern "C" void kernel_launch(void* const* d_in, const int* in_sizes, int n_in,
                              void* d_out, int out_size)
{
    const float* x        = (const float*)d_in[0];  // [16384, 2048]
    const float* w_upgate = (const float*)d_in[1];  // [E*2H, D]
    const float* w_down   = (const float*)d_in[2];  // [D, E*H]
    float* out = (float*)d_out;

    cudaFuncSetAttribute(moe_upgate_kernel,
                         cudaFuncAttributeMaxDynamicSharedMemorySize, SMEM_TOTAL);
    cudaFuncSetAttribute(moe_down_kernel,
                         cudaFuncAttributeMaxDynamicSharedMemorySize, SMEM_TOTAL);

    __half *xh, *ugh, *wdh;
    cudaGetSymbolAddress((void**)&xh,  g_xh);
    cudaGetSymbolAddress((void**)&ugh, g_wugh);
    cudaGetSymbolAddress((void**)&wdh, g_wdh);

    {
        long n4x  = (long)TOTAL_TOKENS * D_MODEL / 4;
        long n4ug = (long)2 * NUM_EXPERTS * HIDDEN * D_MODEL / 4;
        long n4wd = (long)D_MODEL * NUM_EXPERTS * HIDDEN / 4;
        split_h_kernel<<<2048, 256>>>((const float4*)x, (uint2*)xh, n4x);
        split_h_kernel<<<2048, 256>>>((const float4*)w_upgate, (uint2*)ugh, n4ug);
        split_h_kernel<<<2048, 256>>>((const float4*)w_down, (uint2*)wdh, n4wd);
    }

    {
        dim3 grid(HIDDEN / 32, TPE / 256, NUM_EXPERTS);   // (32,8,8)
        moe_upgate_kernel<<<grid, 256, SMEM_TOTAL>>>();
    }
    {
        dim3 grid(D_MODEL / 64, TPE / 256, NUM_EXPERTS);  // (32,8,8)
        moe_down_kernel<<<grid, 256, SMEM_TOTAL>>>(out);
    }
}

// round 16
// speedup vs baseline: 1.9154x; 1.1520x over previous
#include <cuda_runtime.h>
#include <cuda_fp16.h>
#include <cstdint>

#define D_MODEL 2048
#define HIDDEN 1024
#define NUM_EXPERTS 8
#define TPE 2048
#define TOTAL_TOKENS 16384

// fp16 copies (single-pass HMMA everywhere; 5 calibrated rounding sources
// ~2.57e-4 RMS each -> 5.14e-4 measured, under the 1e-3 gate).
__device__ __half g_xh [(size_t)TOTAL_TOKENS * D_MODEL];
__device__ __half g_wugh[(size_t)2 * NUM_EXPERTS * HIDDEN * D_MODEL];
__device__ __half g_wdh [(size_t)D_MODEL * NUM_EXPERTS * HIDDEN];
__device__ __half g_hh  [(size_t)TOTAL_TOKENS * HIDDEN];

// ---------------- helpers ----------------
__device__ __forceinline__ uint32_t SW64(uint32_t off) {
    return off ^ ((off >> 3) & 0x30);
}

__device__ __forceinline__ uint32_t smem_u32(const void* p) {
    return (uint32_t)__cvta_generic_to_shared(p);
}

__device__ __forceinline__ void mma_f16(float* c, const uint32_t* a,
                                        uint32_t b0, uint32_t b1) {
    asm volatile(
        "mma.sync.aligned.m16n8k16.row.col.f32.f16.f16.f32 "
        "{%0,%1,%2,%3}, {%4,%5,%6,%7}, {%8,%9}, {%0,%1,%2,%3};"
        : "+f"(c[0]), "+f"(c[1]), "+f"(c[2]), "+f"(c[3])
        : "r"(a[0]), "r"(a[1]), "r"(a[2]), "r"(a[3]), "r"(b0), "r"(b1));
}

__device__ __forceinline__ void ldsm4(uint32_t r[4], uint32_t saddr) {
    asm volatile("ldmatrix.sync.aligned.m8n8.x4.shared.b16 {%0,%1,%2,%3}, [%4];"
                 : "=r"(r[0]), "=r"(r[1]), "=r"(r[2]), "=r"(r[3]) : "r"(saddr));
}

#define CP_ASYNC16(dst, src) \
    asm volatile("cp.async.cg.shared.global [%0], [%1], 16;" :: "r"(dst), "l"(src))

#define MBAR_INIT(a, n) \
    asm volatile("mbarrier.init.shared.b64 [%0], %1;" :: "r"(a), "r"(n) : "memory")
#define MBAR_ARRIVE(a) \
    asm volatile("mbarrier.arrive.shared.b64 _, [%0];" :: "r"(a) : "memory")
#define CP_MBAR_ARRIVE(a) \
    asm volatile("cp.async.mbarrier.arrive.noinc.shared.b64 [%0];" :: "r"(a) : "memory")

#define MBAR_WAIT(mbar, par) do { \
    uint32_t _m = (mbar); uint32_t _p = (par); uint32_t _d; \
    asm volatile( \
        "{\n\t.reg .pred p;\n\t" \
        "mbarrier.try_wait.parity.acquire.cta.shared::cta.b64 p, [%1], %2;\n\t" \
        "selp.b32 %0, 1, 0, p;\n\t}" \
        : "=r"(_d) : "r"(_m), "r"(_p) : "memory"); \
    if (!_d) { \
        asm volatile( \
            "{\n\t.reg .pred P1;\n\t" \
            "WL_%=:\n\t" \
            "mbarrier.try_wait.parity.acquire.cta.shared::cta.b64 P1, [%0], %1, 0x989680;\n\t" \
            "@P1 bra.uni WD_%=;\n\t" \
            "bra.uni WL_%=;\n\t" \
            "WD_%=:\n\t}" \
            :: "r"(_m), "r"(_p) : "memory"); \
    } \
} while (0)

__device__ __forceinline__ float silu(float x) {
    return x / (1.0f + __expf(-x));
}

// Stage (one k32): A[0,16K) fp16 (256 rows x 64B), B[16K,20K) (64 rows x 64B)
#define STAGE 20480
#define BAR_OFF (4 * STAGE)              // full[s]=+s*8, empty[s]=+32+s*8
#define SMEM_TOTAL (4 * STAGE + 128)     // ~80 KB -> 2 CTAs/SM

// Precomputed swizzled ldsm offsets: [ks][frag]
struct LdsmOffs {
    uint32_t a[2][4];
    uint32_t b[2][2];
};

__device__ __forceinline__ LdsmOffs make_offs(int lane, int mw, int nw) {
    LdsmOffs o;
    const int r = lane & 15;
    const uint32_t h16 = (uint32_t)(lane >> 4) << 4;
    #pragma unroll
    for (int ks = 0; ks < 2; ks++) {
        const uint32_t kc = (uint32_t)ks * 32 + h16;
        #pragma unroll
        for (int mt = 0; mt < 4; mt++) {
            uint32_t R = (uint32_t)(mw * 64 + mt * 16 + r) * 64;
            o.a[ks][mt] = R + (kc ^ ((R >> 3) & 0x30));
        }
        #pragma unroll
        for (int pr = 0; pr < 2; pr++) {
            uint32_t R = (uint32_t)(nw * 32 + pr * 16 + r) * 64;
            o.b[ks][pr] = 16384u + R + (kc ^ ((R >> 3) & 0x30));
        }
    }
    return o;
}

// ---------------- split kernel: fp32 -> fp16 ----------------
__global__ void split_h_kernel(const float4* __restrict__ src,
                               uint2* __restrict__ dst, long n4)
{
    for (long i = (long)blockIdx.x * blockDim.x + threadIdx.x; i < n4;
         i += (long)gridDim.x * blockDim.x) {
        float4 v = src[i];
        __half2 p0(__float2half_rn(v.x), __float2half_rn(v.y));
        __half2 p1(__float2half_rn(v.z), __float2half_rn(v.w));
        uint2 o;
        o.x = *reinterpret_cast<uint32_t*>(&p0);
        o.y = *reinterpret_cast<uint32_t*>(&p1);
        dst[i] = o;
    }
}

// ---------------- compute one k32 stage; arrive empty after last LDSM -------
__device__ __forceinline__ void compute_k32_mb(uint32_t st, float acc[4][4][4],
                                               const LdsmOffs& o, uint32_t ebar)
{
    uint32_t a0[4][4], b0[2][4];
    #pragma unroll
    for (int mt = 0; mt < 4; mt++) ldsm4(a0[mt], st + o.a[0][mt]);
    #pragma unroll
    for (int pr = 0; pr < 2; pr++) ldsm4(b0[pr], st + o.b[0][pr]);

    #pragma unroll
    for (int mt = 0; mt < 4; mt++)
        #pragma unroll
        for (int nt = 0; nt < 4; nt++)
            mma_f16(acc[mt][nt], a0[mt], b0[nt >> 1][nt & 1], b0[nt >> 1][(nt & 1) + 2]);

    uint32_t a1[4][4], b1[2][4];
    #pragma unroll
    for (int mt = 0; mt < 4; mt++) ldsm4(a1[mt], st + o.a[1][mt]);
    #pragma unroll
    for (int pr = 0; pr < 2; pr++) ldsm4(b1[pr], st + o.b[1][pr]);

    MBAR_ARRIVE(ebar);   // stage reads done (frags in regs)

    #pragma unroll
    for (int mt = 0; mt < 4; mt++)
        #pragma unroll
        for (int nt = 0; nt < 4; nt++)
            mma_f16(acc[mt][nt], a1[mt], b1[nt >> 1][nt & 1], b1[nt >> 1][(nt & 1) + 2]);
}

// ---------------- kernel 1: h = silu(x@Wg^T) * (x@Wu^T) ----------------
// CTA: 256 tokens x 64 B-rows (32 h-cols; gate/up interleaved per 16 rows).
// 8 warps = 4 mw x 2 nw; warp tile 64 x 32. mbarrier pipeline, no __syncthreads
// in the main loop -> warps drift and interleave LDSM/MMA phases.
__global__ __launch_bounds__(256, 2)
void moe_upgate_kernel()
{
    extern __shared__ char smem[];
    const uint32_t smem_b = smem_u32(smem);
    const uint32_t FB = smem_b + BAR_OFF;        // full[s] = FB + s*8
    const uint32_t EB = smem_b + BAR_OFF + 32;   // empty[s] = EB + s*8

    const int tid = threadIdx.x;
    const int lane = tid & 31, warp = tid >> 5;
    const int g = lane >> 2, tg = lane & 3;
    const int nw = warp & 1, mw = warp >> 1;

    const int e = blockIdx.z;
    const int m0 = blockIdx.y * 256;
    const int n0 = blockIdx.x * 32;

    const long arow0 = (long)e * TPE + m0;
    const long brow0 = (long)e * 2 * HIDDEN;

    const int trow = tid >> 2, tc16 = tid & 3;
    uint32_t dA[4];
    #pragma unroll
    for (int it = 0; it < 4; it++)
        dA[it] = SW64((uint32_t)((trow + it * 64) * 64 + tc16 * 16));
    const uint32_t dB = SW64((uint32_t)(trow * 64 + tc16 * 16));

    const __half* pA = g_xh + (arow0 + trow) * D_MODEL + tc16 * 8;
    const int nwr = trow >> 5, jj = trow & 31, pgu = jj >> 4, cc = jj & 15;
    const long grow = brow0 + (pgu ? HIDDEN : 0) + n0 + nwr * 16 + cc;
    const __half* pB = g_wugh + grow * D_MODEL + tc16 * 8;

    const LdsmOffs offs = make_offs(lane, mw, nw);

    #define ISSUE_UG(SIDX, PA, PB) do { \
        uint32_t _s = smem_b + (uint32_t)(SIDX) * STAGE; \
        _Pragma("unroll") \
        for (int _it = 0; _it < 4; _it++) \
            CP_ASYNC16(_s + dA[_it], (PA) + (long)_it * 64 * D_MODEL); \
        CP_ASYNC16(_s + 16384 + dB, (PB)); \
    } while (0)

    // barrier init + pre-arm empties
    if (tid == 0) {
        #pragma unroll
        for (int s = 0; s < 4; s++) {
            MBAR_INIT(FB + s * 8, 256);
            MBAR_INIT(EB + s * 8, 256);
        }
    }
    __syncthreads();
    #pragma unroll
    for (int s = 0; s < 4; s++) MBAR_ARRIVE(EB + s * 8);

    float acc[4][4][4];
    #pragma unroll
    for (int i = 0; i < 4; i++)
        #pragma unroll
        for (int j = 0; j < 4; j++)
            #pragma unroll
            for (int k = 0; k < 4; k++) acc[i][j][k] = 0.0f;

    // prologue: fills #0 of stages 0..2 (chunks 0,1,2)
    MBAR_WAIT(EB + 0,  0); ISSUE_UG(0, pA,      pB);      CP_MBAR_ARRIVE(FB + 0);
    MBAR_WAIT(EB + 8,  0); ISSUE_UG(1, pA + 32, pB + 32); CP_MBAR_ARRIVE(FB + 8);
    MBAR_WAIT(EB + 16, 0); ISSUE_UG(2, pA + 64, pB + 64); CP_MBAR_ARRIVE(FB + 16);

    const int NQUAD = (D_MODEL / 32) / 4;   // 16
    for (int q = 0; q < NQUAD; q++) {
        const uint32_t Pq = (uint32_t)(q & 1), Pq1 = Pq ^ 1u;

        // chunk 4q: consume stage 0; produce chunk 4q+3 -> stage 3 (fill q)
        MBAR_WAIT(FB + 0, Pq);
        compute_k32_mb(smem_b + 0 * STAGE, acc, offs, EB + 0);
        MBAR_WAIT(EB + 24, Pq);
        ISSUE_UG(3, pA + 96, pB + 96);
        CP_MBAR_ARRIVE(FB + 24);

        // chunk 4q+1: consume stage 1; produce -> stage 0 (fill q+1)
        MBAR_WAIT(FB + 8, Pq);
        compute_k32_mb(smem_b + 1 * STAGE, acc, offs, EB + 8);
        if (q + 1 < NQUAD) {
            MBAR_WAIT(EB + 0, Pq1);
            ISSUE_UG(0, pA + 128, pB + 128);
            CP_MBAR_ARRIVE(FB + 0);
        }

        // chunk 4q+2: consume stage 2; produce -> stage 1 (fill q+1)
        MBAR_WAIT(FB + 16, Pq);
        compute_k32_mb(smem_b + 2 * STAGE, acc, offs, EB + 16);
        if (q + 1 < NQUAD) {
            MBAR_WAIT(EB + 8, Pq1);
            ISSUE_UG(1, pA + 160, pB + 160);
            CP_MBAR_ARRIVE(FB + 8);
        }

        // chunk 4q+3: consume stage 3; produce -> stage 2 (fill q+1)
        MBAR_WAIT(FB + 24, Pq);
        compute_k32_mb(smem_b + 3 * STAGE, acc, offs, EB + 24);
        if (q + 1 < NQUAD) {
            MBAR_WAIT(EB + 16, Pq1);
            ISSUE_UG(2, pA + 192, pB + 192);
            CP_MBAR_ARRIVE(FB + 16);
        }

        pA += 128;
        pB += 128;
    }
    #undef ISSUE_UG

    // epilogue: acc[mt][ntl] = gate (pr=0), acc[mt][2+ntl] = up (pr=1)
    #pragma unroll
    for (int mt = 0; mt < 4; mt++) {
        long row0 = arow0 + mw * 64 + mt * 16 + g;
        #pragma unroll
        for (int ntl = 0; ntl < 2; ntl++) {
            const float* ga = acc[mt][ntl];
            const float* ua = acc[mt][2 + ntl];
            int col = n0 + nw * 16 + ntl * 8 + tg * 2;
            __half2 v0(__float2half_rn(silu(ga[0]) * ua[0]),
                       __float2half_rn(silu(ga[1]) * ua[1]));
            __half2 v1(__float2half_rn(silu(ga[2]) * ua[2]),
                       __float2half_rn(silu(ga[3]) * ua[3]));
            *reinterpret_cast<__half2*>(g_hh + row0 * HIDDEN + col) = v0;
            *reinterpret_cast<__half2*>(g_hh + (row0 + 8) * HIDDEN + col) = v1;
        }
    }
}

// ---------------- kernel 2: out = h @ Wd^T ----------------
__global__ __launch_bounds__(256, 2)
void moe_down_kernel(float* __restrict__ out)
{
    extern __shared__ char smem[];
    const uint32_t smem_b = smem_u32(smem);
    const uint32_t FB = smem_b + BAR_OFF;
    const uint32_t EB = smem_b + BAR_OFF + 32;

    const int tid = threadIdx.x;
    const int lane = tid & 31, warp = tid >> 5;
    const int g = lane >> 2, tg = lane & 3;
    const int nw = warp & 1, mw = warp >> 1;

    const int e = blockIdx.z;
    const int m0 = blockIdx.y * 256;
    const int n0 = blockIdx.x * 64;

    const long arow0 = (long)e * TPE + m0;

    const int trow = tid >> 2, tc16 = tid & 3;
    uint32_t dA[4];
    #pragma unroll
    for (int it = 0; it < 4; it++)
        dA[it] = SW64((uint32_t)((trow + it * 64) * 64 + tc16 * 16));
    const uint32_t dB = SW64((uint32_t)(trow * 64 + tc16 * 16));

    const __half* pA = g_hh + (arow0 + trow) * HIDDEN + tc16 * 8;
    const long browb = (long)(n0 + trow) * (NUM_EXPERTS * HIDDEN) + (long)e * HIDDEN;
    const __half* pB = g_wdh + browb + tc16 * 8;

    const LdsmOffs offs = make_offs(lane, mw, nw);

    #define ISSUE_DN(SIDX, PA, PB) do { \
        uint32_t _s = smem_b + (uint32_t)(SIDX) * STAGE; \
        _Pragma("unroll") \
        for (int _it = 0; _it < 4; _it++) \
            CP_ASYNC16(_s + dA[_it], (PA) + (long)_it * 64 * HIDDEN); \
        CP_ASYNC16(_s + 16384 + dB, (PB)); \
    } while (0)

    if (tid == 0) {
        #pragma unroll
        for (int s = 0; s < 4; s++) {
            MBAR_INIT(FB + s * 8, 256);
            MBAR_INIT(EB + s * 8, 256);
        }
    }
    __syncthreads();
    #pragma unroll
    for (int s = 0; s < 4; s++) MBAR_ARRIVE(EB + s * 8);

    float acc[4][4][4];
    #pragma unroll
    for (int i = 0; i < 4; i++)
        #pragma unroll
        for (int j = 0; j < 4; j++)
            #pragma unroll
            for (int k = 0; k < 4; k++) acc[i][j][k] = 0.0f;

    MBAR_WAIT(EB + 0,  0); ISSUE_DN(0, pA,      pB);      CP_MBAR_ARRIVE(FB + 0);
    MBAR_WAIT(EB + 8,  0); ISSUE_DN(1, pA + 32, pB + 32); CP_MBAR_ARRIVE(FB + 8);
    MBAR_WAIT(EB + 16, 0); ISSUE_DN(2, pA + 64, pB + 64); CP_MBAR_ARRIVE(FB + 16);

    const int NQUAD = (HIDDEN / 32) / 4;    // 8
    for (int q = 0; q < NQUAD; q++) {
        const uint32_t Pq = (uint32_t)(q & 1), Pq1 = Pq ^ 1u;

        MBAR_WAIT(FB + 0, Pq);
        compute_k32_mb(smem_b + 0 * STAGE, acc, offs, EB + 0);
        MBAR_WAIT(EB + 24, Pq);
        ISSUE_DN(3, pA + 96, pB + 96);
        CP_MBAR_ARRIVE(FB + 24);

        MBAR_WAIT(FB + 8, Pq);
        compute_k32_mb(smem_b + 1 * STAGE, acc, offs, EB + 8);
        if (q + 1 < NQUAD) {
            MBAR_WAIT(EB + 0, Pq1);
            ISSUE_DN(0, pA + 128, pB + 128);
            CP_MBAR_ARRIVE(FB + 0);
        }

        MBAR_WAIT(FB + 16, Pq);
        compute_k32_mb(smem_b + 2 * STAGE, acc, offs, EB + 16);
        if (q + 1 < NQUAD) {
            MBAR_WAIT(EB + 8, Pq1);
            ISSUE_DN(1, pA + 160, pB + 160);
            CP_MBAR_ARRIVE(FB + 8);
        }

        MBAR_WAIT(FB + 24, Pq);
        compute_k32_mb(smem_b + 3 * STAGE, acc, offs, EB + 24);
        if (q + 1 < NQUAD) {
            MBAR_WAIT(EB + 16, Pq1);
            ISSUE_DN(2, pA + 192, pB + 192);
            CP_MBAR_ARRIVE(FB + 16);
        }

        pA += 128;
        pB += 128;
    }
    #undef ISSUE_DN

    #pragma unroll
    for (int mt = 0; mt < 4; mt++) {
        long row0 = arow0 + mw * 64 + mt * 16 + g;
        #pragma unroll
        for (int nt = 0; nt < 4; nt++) {
            int col = n0 + nw * 32 + (nt >> 1) * 16 + (nt & 1) * 8 + tg * 2;
            float2 v0, v1;
            v0.x = acc[mt][nt][0]; v0.y = acc[mt][nt][1];
            v1.x = acc[mt][nt][2]; v1.y = acc[mt][nt][3];
            *reinterpret_cast<float2*>(out + row0 * D_MODEL + col) = v0;
            *reinterpret_cast<float2*>(out + (row0 + 8) * D_MODEL + col) = v1;
        }
    }
}

// ---------------- launch ----------------
extern "C" void kernel_launch(void* const* d_in, const int* in_sizes, int n_in,
                              void* d_out, int out_size)
{
    const float* x        = (const float*)d_in[0];  // [16384, 2048]
    const float* w_upgate = (const float*)d_in[1];  // [E*2H, D]
    const float* w_down   = (const float*)d_in[2];  // [D, E*H]
    float* out = (float*)d_out;

    cudaFuncSetAttribute(moe_upgate_kernel,
                         cudaFuncAttributeMaxDynamicSharedMemorySize, SMEM_TOTAL);
    cudaFuncSetAttribute(moe_down_kernel,
                         cudaFuncAttributeMaxDynamicSharedMemorySize, SMEM_TOTAL);

    __half *xh, *ugh, *wdh;
    cudaGetSymbolAddress((void**)&xh,  g_xh);
    cudaGetSymbolAddress((void**)&ugh, g_wugh);
    cudaGetSymbolAddress((void**)&wdh, g_wdh);

    {
        long n4x  = (long)TOTAL_TOKENS * D_MODEL / 4;
        long n4ug = (long)2 * NUM_EXPERTS * HIDDEN * D_MODEL / 4;
        long n4wd = (long)D_MODEL * NUM_EXPERTS * HIDDEN / 4;
        split_h_kernel<<<2048, 256>>>((const float4*)x, (uint2*)xh, n4x);
        split_h_kernel<<<2048, 256>>>((const float4*)w_upgate, (uint2*)ugh, n4ug);
        split_h_kernel<<<2048, 256>>>((const float4*)w_down, (uint2*)wdh, n4wd);
    }

    {
        dim3 grid(HIDDEN / 32, TPE / 256, NUM_EXPERTS);   // (32,8,8)
        moe_upgate_kernel<<<grid, 256, SMEM_TOTAL>>>();
    }
    {
        dim3 grid(D_MODEL / 64, TPE / 256, NUM_EXPERTS);  // (32,8,8)
        moe_down_kernel<<<grid, 256, SMEM_TOTAL>>>(out);
    }
}